// round 16
// baseline (speedup 1.0000x reference)
#include <cuda_runtime.h>
#include <cuda_bf16.h>
#include <cstdint>
#include <math.h>

#define BB 2
#define SS 2048
#define DD 2048
#define HH 16
#define FF 128
#define EPSV 1e-6f

#define QSCALE 0.1275174431f
#define SOFF 16.5f

// ---------------- scratch (static device memory; no allocations) ----------------
__device__ float g_cos[2048 * 64];
__device__ float g_sin[2048 * 64];
__device__ uint32_t g_xqhi[4096 * 1024];
__device__ uint32_t g_xqlo[4096 * 1024];
__device__ uint32_t g_xkhi[4096 * 1024];
__device__ uint32_t g_xklo[4096 * 1024];
__device__ uint32_t g_xvhi[4096 * 1024];
__device__ uint32_t g_xvlo[4096 * 1024];
__device__ uint32_t g_w0hi[1024 * 2048];
__device__ uint32_t g_w0lo[1024 * 2048];
__device__ uint32_t g_w1hi[1024 * 2048];
__device__ uint32_t g_w1lo[1024 * 2048];
__device__ uint32_t g_w2hi[1024 * 2048];
__device__ uint32_t g_w2lo[1024 * 2048];
__device__ uint32_t g_wohi[1024 * 2048];
__device__ uint32_t g_wolo[1024 * 2048];
__device__ uint32_t g_qhi[4096 * 1024];
__device__ uint32_t g_qlo[4096 * 1024];
__device__ uint32_t g_khi[4096 * 1024];
__device__ uint32_t g_klo[4096 * 1024];
__device__ uint32_t g_vthi[2 * 2048 * 1024];
__device__ uint32_t g_vtlo[2 * 2048 * 1024];
__device__ float g_part[2 * 4096 * 2048];
__device__ float g_lsum[2 * 4096 * 16];
__device__ uint32_t g_ahi[4096 * 1024];
__device__ uint32_t g_alo[4096 * 1024];

// ---------------- helpers ---------------------------------------------------------
__device__ __forceinline__ uint32_t pack2(__nv_bfloat16 a, __nv_bfloat16 b) {
    __nv_bfloat162 h2;
    h2.x = a; h2.y = b;
    return *reinterpret_cast<uint32_t*>(&h2);
}

__device__ __forceinline__ void split_pair(float e0, float e1, uint32_t& hi, uint32_t& lo) {
    __nv_bfloat16 h0 = __float2bfloat16_rn(e0);
    __nv_bfloat16 h1 = __float2bfloat16_rn(e1);
    float l0 = e0 - __bfloat162float(h0);
    float l1 = e1 - __bfloat162float(h1);
    hi = pack2(h0, h1);
    lo = pack2(__float2bfloat16_rn(l0), __float2bfloat16_rn(l1));
}

__device__ __forceinline__ float fexp2(float x) {
    float r;
    asm("ex2.approx.f32 %0, %1;" : "=f"(r) : "f"(x));
    return r;
}

__device__ __forceinline__ void mma16816(float* c, uint32_t a0, uint32_t a1, uint32_t a2,
                                         uint32_t a3, uint32_t b0, uint32_t b1) {
    asm volatile(
        "mma.sync.aligned.m16n8k16.row.col.f32.bf16.bf16.f32 "
        "{%0,%1,%2,%3},{%4,%5,%6,%7},{%8,%9},{%0,%1,%2,%3};\n"
        : "+f"(c[0]), "+f"(c[1]), "+f"(c[2]), "+f"(c[3])
        : "r"(a0), "r"(a1), "r"(a2), "r"(a3), "r"(b0), "r"(b1));
}

__device__ __forceinline__ void cpa16(uint32_t dst, const void* src) {
    asm volatile("cp.async.cg.shared.global [%0], [%1], 16;\n" :: "r"(dst), "l"(src));
}

// ---------------- RoPE table -----------------------------------------------------
__global__ void rope_table_kernel(float* __restrict__ cosT, float* __restrict__ sinT) {
    int idx = blockIdx.x * 256 + threadIdx.x;
    if (idx >= 2048 * 64) return;
    int p = idx / 64, i = idx % 64;
    float freq = (float)(1.0 / pow(10000.0, (double)i / 64.0));
    float a = (float)p * freq;
    cosT[idx] = (float)cos((double)a);
    sinT[idx] = (float)sin((double)a);
}

// ---------------- vectorized pre-split kernels -----------------------------------
__global__ void split_rows3_kernel(const float* __restrict__ x0, const float* __restrict__ x1,
                                   const float* __restrict__ x2,
                                   uint32_t* __restrict__ h0, uint32_t* __restrict__ l0,
                                   uint32_t* __restrict__ h1, uint32_t* __restrict__ l1,
                                   uint32_t* __restrict__ h2, uint32_t* __restrict__ l2) {
    int s = blockIdx.z;
    const float4* x = (const float4*)((s == 0) ? x0 : (s == 1) ? x1 : x2);
    uint2* xh = (uint2*)((s == 0) ? h0 : (s == 1) ? h1 : h2);
    uint2* xl = (uint2*)((s == 0) ? l0 : (s == 1) ? l1 : l2);
    int base = blockIdx.x * 1024 + threadIdx.x;
    float4 v[4];
#pragma unroll
    for (int j = 0; j < 4; j++) v[j] = x[base + j * 256];
#pragma unroll
    for (int j = 0; j < 4; j++) {
        uint2 hi, lo;
        split_pair(v[j].x, v[j].y, hi.x, lo.x);
        split_pair(v[j].z, v[j].w, hi.y, lo.y);
        xh[base + j * 256] = hi;
        xl[base + j * 256] = lo;
    }
}

__global__ void wsplit3_kernel(const float* __restrict__ W0, const float* __restrict__ W1,
                               const float* __restrict__ W2,
                               uint32_t* __restrict__ h0, uint32_t* __restrict__ l0,
                               uint32_t* __restrict__ h1, uint32_t* __restrict__ l1,
                               uint32_t* __restrict__ h2, uint32_t* __restrict__ l2) {
    int s = blockIdx.z;
    const float* W = (s == 0) ? W0 : (s == 1) ? W1 : W2;
    uint32_t* wh = (s == 0) ? h0 : (s == 1) ? h1 : h2;
    uint32_t* wl = (s == 0) ? l0 : (s == 1) ? l1 : l2;
    int T = blockIdx.x * 256 + threadIdx.x;
    int n4 = T & 511, kp2 = T >> 9;
    int n = n4 * 4, h = n >> 7, f = n & 127;
    const float* base = W + ((long)h * 2048 + kp2 * 4) * 128 + f;
    float4 r0 = *(const float4*)(base);
    float4 r1 = *(const float4*)(base + 128);
    float4 r2 = *(const float4*)(base + 256);
    float4 r3 = *(const float4*)(base + 384);
    uint4 ha, la, hb, lb;
    split_pair(r0.x, r1.x, ha.x, la.x);
    split_pair(r0.y, r1.y, ha.y, la.y);
    split_pair(r0.z, r1.z, ha.z, la.z);
    split_pair(r0.w, r1.w, ha.w, la.w);
    split_pair(r2.x, r3.x, hb.x, lb.x);
    split_pair(r2.y, r3.y, hb.y, lb.y);
    split_pair(r2.z, r3.z, hb.z, lb.z);
    split_pair(r2.w, r3.w, hb.w, lb.w);
    long o0 = (long)(kp2 * 2) * 2048 + n;
    *(uint4*)&wh[o0] = ha;
    *(uint4*)&wl[o0] = la;
    *(uint4*)&wh[o0 + 2048] = hb;
    *(uint4*)&wl[o0 + 2048] = lb;
}

__global__ void wosplit_kernel(const float* __restrict__ WO,
                               uint32_t* __restrict__ whi, uint32_t* __restrict__ wlo) {
    int T = blockIdx.x * 256 + threadIdx.x;
    int m4 = T & 511, kp2 = T >> 9;
    int m = m4 * 4;
    const float* base = WO + (long)(kp2 * 4) * 2048 + m;
    float4 r0 = *(const float4*)(base);
    float4 r1 = *(const float4*)(base + 2048);
    float4 r2 = *(const float4*)(base + 4096);
    float4 r3 = *(const float4*)(base + 6144);
    uint4 ha, la, hb, lb;
    split_pair(r0.x, r1.x, ha.x, la.x);
    split_pair(r0.y, r1.y, ha.y, la.y);
    split_pair(r0.z, r1.z, ha.z, la.z);
    split_pair(r0.w, r1.w, ha.w, la.w);
    split_pair(r2.x, r3.x, hb.x, lb.x);
    split_pair(r2.y, r3.y, hb.y, lb.y);
    split_pair(r2.z, r3.z, hb.z, lb.z);
    split_pair(r2.w, r3.w, hb.w, lb.w);
    long o0 = (long)(kp2 * 2) * 2048 + m;
    *(uint4*)&whi[o0] = ha;
    *(uint4*)&wlo[o0] = la;
    *(uint4*)&whi[o0 + 2048] = hb;
    *(uint4*)&wlo[o0 + 2048] = lb;
}

// ---------------- GEMM config ------------------------------------------------------
#define G2_AS_LO 10240
#define G2_BS_HI 20480
#define G2_BS_LO 29184
#define G2_STAGE 37888
#define G2_SMEM  75776

#define GEMM_MAINLOOP(Ahi, Alo, Bhi, Blo)                                                   \
    auto prefetch = [&](int t) {                                                            \
        uint32_t sb = smem_base + (t & 1) * G2_STAGE;                                       \
        _Pragma("unroll")                                                                   \
        for (int i = 0; i < 2; i++) {                                                       \
            int c = tid + i * 256;                                                          \
            int row = c >> 2, q4 = (c & 3) * 4;                                             \
            cpa16(sb + (row * 20 + q4) * 4, Ahi + (long)(bm + row) * 1024 + t * 16 + q4);   \
            cpa16(sb + G2_AS_LO + (row * 20 + q4) * 4,                                      \
                  Alo + (long)(bm + row) * 1024 + t * 16 + q4);                             \
        }                                                                                   \
        _Pragma("unroll")                                                                   \
        for (int i = 0; i < 2; i++) {                                                       \
            int c = tid + i * 256;                                                          \
            int kp = c >> 5, n4 = (c & 31) * 4;                                             \
            cpa16(sb + G2_BS_HI + (kp * 136 + n4) * 4,                                      \
                  Bhi + (long)(t * 16 + kp) * 2048 + bn + n4);                              \
            cpa16(sb + G2_BS_LO + (kp * 136 + n4) * 4,                                      \
                  Blo + (long)(t * 16 + kp) * 2048 + bn + n4);                              \
        }                                                                                   \
        asm volatile("cp.async.commit_group;\n" ::: "memory");                              \
    };                                                                                      \
    prefetch(0);                                                                            \
    for (int t = 0; t < 64; t++) {                                                          \
        if (t + 1 < 64) {                                                                   \
            prefetch(t + 1);                                                                \
            asm volatile("cp.async.wait_group 1;\n" ::: "memory");                          \
        } else {                                                                            \
            asm volatile("cp.async.wait_group 0;\n" ::: "memory");                          \
        }                                                                                   \
        __syncthreads();                                                                    \
        const uint32_t* ash = (const uint32_t*)(gsm + (t & 1) * G2_STAGE);                  \
        const uint32_t* asl = (const uint32_t*)(gsm + (t & 1) * G2_STAGE + G2_AS_LO);       \
        const uint32_t* bsh = (const uint32_t*)(gsm + (t & 1) * G2_STAGE + G2_BS_HI);       \
        const uint32_t* bsl = (const uint32_t*)(gsm + (t & 1) * G2_STAGE + G2_BS_LO);       \
        _Pragma("unroll")                                                                   \
        for (int ks = 0; ks < 2; ks++) {                                                    \
            const int kp0 = ks * 8 + t4;                                                    \
            uint32_t bh0[4], bh1[4], bl0[4], bl1[4];                                        \
            _Pragma("unroll")                                                               \
            for (int ct = 0; ct < 4; ct++) {                                                \
                int col = wn + ct * 8 + g;                                                  \
                bh0[ct] = bsh[kp0 * 136 + col];                                             \
                bh1[ct] = bsh[(kp0 + 4) * 136 + col];                                       \
                bl0[ct] = bsl[kp0 * 136 + col];                                             \
                bl1[ct] = bsl[(kp0 + 4) * 136 + col];                                       \
            }                                                                               \
            _Pragma("unroll")                                                               \
            for (int rt = 0; rt < 4; rt++) {                                                \
                int row = wm + rt * 16 + g;                                                 \
                uint32_t ah0 = ash[row * 20 + kp0];                                         \
                uint32_t ah1 = ash[(row + 8) * 20 + kp0];                                   \
                uint32_t ah2 = ash[row * 20 + kp0 + 4];                                     \
                uint32_t ah3 = ash[(row + 8) * 20 + kp0 + 4];                               \
                uint32_t al0 = asl[row * 20 + kp0];                                         \
                uint32_t al1 = asl[(row + 8) * 20 + kp0];                                   \
                uint32_t al2 = asl[row * 20 + kp0 + 4];                                     \
                uint32_t al3 = asl[(row + 8) * 20 + kp0 + 4];                               \
                _Pragma("unroll")                                                           \
                for (int ct = 0; ct < 4; ct++) {                                            \
                    mma16816(acc[rt][ct], ah0, ah1, ah2, ah3, bh0[ct], bh1[ct]);            \
                    mma16816(acc[rt][ct], ah0, ah1, ah2, ah3, bl0[ct], bl1[ct]);            \
                    mma16816(acc[rt][ct], al0, al1, al2, al3, bh0[ct], bh1[ct]);            \
                }                                                                           \
            }                                                                               \
        }                                                                                   \
        __syncthreads();                                                                    \
    }

// plain GEMM (fp32 out + bias): O projection
__global__ __launch_bounds__(256, 2)
void bgemm2_kernel(const uint32_t* __restrict__ Ahi, const uint32_t* __restrict__ Alo,
                   const uint32_t* __restrict__ Bhi, const uint32_t* __restrict__ Blo,
                   float* __restrict__ C, const float* __restrict__ bias) {
    extern __shared__ char gsm[];
    const uint32_t smem_base = (uint32_t)__cvta_generic_to_shared(gsm);
    const int tid = threadIdx.x;
    const int lane = tid & 31;
    const int warp = tid >> 5;
    const int wm = (warp >> 2) * 64;
    const int wn = (warp & 3) * 32;
    const int g = lane >> 2;
    const int t4 = lane & 3;
    const int bm = blockIdx.y * 128, bn = blockIdx.x * 128;

    float acc[4][4][4];
#pragma unroll
    for (int i = 0; i < 4; i++)
#pragma unroll
        for (int j = 0; j < 4; j++)
#pragma unroll
            for (int r = 0; r < 4; r++) acc[i][j][r] = 0.f;

    GEMM_MAINLOOP(Ahi, Alo, Bhi, Blo)

#pragma unroll
    for (int rt = 0; rt < 4; rt++) {
        int row0 = bm + wm + rt * 16 + g;
#pragma unroll
        for (int ct = 0; ct < 4; ct++) {
            int col0 = bn + wn + ct * 8 + 2 * t4;
            float b0 = bias[col0], b1 = bias[col0 + 1];
            float2 v0 = make_float2(acc[rt][ct][0] + b0, acc[rt][ct][1] + b1);
            float2 v1 = make_float2(acc[rt][ct][2] + b0, acc[rt][ct][3] + b1);
            *(float2*)(C + (long)row0 * 2048 + col0) = v0;
            *(float2*)(C + (long)(row0 + 8) * 2048 + col0) = v1;
        }
    }
}

// GEMM + fused RMSNorm + RoPE + split epilogue (Q: z=0, K: z=1)
__global__ __launch_bounds__(256, 2)
void bgemm_nr_kernel(const uint32_t* __restrict__ Aqhi, const uint32_t* __restrict__ Aqlo,
                     const uint32_t* __restrict__ Bqhi, const uint32_t* __restrict__ Bqlo,
                     const float* __restrict__ bq, const float* __restrict__ wq,
                     const uint32_t* __restrict__ Akhi, const uint32_t* __restrict__ Aklo,
                     const uint32_t* __restrict__ Bkhi, const uint32_t* __restrict__ Bklo,
                     const float* __restrict__ bk, const float* __restrict__ wk,
                     const float* __restrict__ cosT, const float* __restrict__ sinT,
                     uint32_t* __restrict__ qhi, uint32_t* __restrict__ qlo,
                     uint32_t* __restrict__ khi, uint32_t* __restrict__ klo) {
    extern __shared__ char gsm[];
    __shared__ float rsum[128][4];
    const uint32_t smem_base = (uint32_t)__cvta_generic_to_shared(gsm);

    int z = blockIdx.z;
    const uint32_t* Ahi = z ? Akhi : Aqhi;
    const uint32_t* Alo = z ? Aklo : Aqlo;
    const uint32_t* Bhi = z ? Bkhi : Bqhi;
    const uint32_t* Blo = z ? Bklo : Bqlo;
    const float* bias = z ? bk : bq;
    const float* w = z ? wk : wq;
    uint32_t* ohi = z ? khi : qhi;
    uint32_t* olo = z ? klo : qlo;
    const float scale = z ? 1.f : QSCALE;

    const int tid = threadIdx.x;
    const int lane = tid & 31;
    const int warp = tid >> 5;
    const int wm = (warp >> 2) * 64;
    const int wn = (warp & 3) * 32;
    const int g = lane >> 2;
    const int t4 = lane & 3;
    const int bm = blockIdx.y * 128, bn = blockIdx.x * 128;

    float acc[4][4][4];
#pragma unroll
    for (int i = 0; i < 4; i++)
#pragma unroll
        for (int j = 0; j < 4; j++)
#pragma unroll
            for (int r = 0; r < 4; r++) acc[i][j][r] = 0.f;

    GEMM_MAINLOOP(Ahi, Alo, Bhi, Blo)

    float ss[4][2];
#pragma unroll
    for (int rt = 0; rt < 4; rt++) {
#pragma unroll
        for (int half = 0; half < 2; half++) {
            float s = 0.f;
#pragma unroll
            for (int ct = 0; ct < 4; ct++) {
                int col0 = bn + wn + ct * 8 + 2 * t4;
                float v0 = acc[rt][ct][2 * half] + bias[col0];
                float v1 = acc[rt][ct][2 * half + 1] + bias[col0 + 1];
                acc[rt][ct][2 * half] = v0;
                acc[rt][ct][2 * half + 1] = v1;
                s += v0 * v0 + v1 * v1;
            }
            s += __shfl_xor_sync(0xffffffffu, s, 1);
            s += __shfl_xor_sync(0xffffffffu, s, 2);
            ss[rt][half] = s;
        }
    }
    if (t4 == 0) {
#pragma unroll
        for (int rt = 0; rt < 4; rt++) {
#pragma unroll
            for (int half = 0; half < 2; half++)
                rsum[wm + rt * 16 + g + half * 8][warp & 3] = ss[rt][half];
        }
    }
    __syncthreads();

    float* sv = (float*)gsm;
#pragma unroll
    for (int rt = 0; rt < 4; rt++) {
#pragma unroll
        for (int half = 0; half < 2; half++) {
            int r = wm + rt * 16 + g + half * 8;
            float tot = rsum[r][0] + rsum[r][1] + rsum[r][2] + rsum[r][3];
            float inv = 1.f / (sqrtf(tot * (1.f / 128.f)) + EPSV);
#pragma unroll
            for (int ct = 0; ct < 4; ct++) {
                int f = wn + ct * 8 + 2 * t4;
                sv[r * 132 + f] = acc[rt][ct][2 * half] * inv * __ldg(&w[f]);
                sv[r * 132 + f + 1] = acc[rt][ct][2 * half + 1] * inv * __ldg(&w[f + 1]);
            }
        }
    }
    __syncthreads();

    const int h = bn >> 7;
#pragma unroll
    for (int rt = 0; rt < 4; rt++) {
#pragma unroll
        for (int half = 0; half < 2; half++) {
            int r = wm + rt * 16 + g + half * 8;
            int p = (bm + r) & (SS - 1);
            long orow = (long)(bm + r) * 1024 + h * 64;
#pragma unroll
            for (int ct = 0; ct < 4; ct++) {
                int f0 = wn + ct * 8 + 2 * t4;
                int i0 = f0 & 63;
                float2 cs = *(const float2*)(cosT + p * 64 + i0);
                float2 sn = *(const float2*)(sinT + p * 64 + i0);
                float me0 = sv[r * 132 + f0];
                float me1 = sv[r * 132 + f0 + 1];
                float pr0 = sv[r * 132 + (f0 ^ 64)];
                float pr1 = sv[r * 132 + ((f0 + 1) ^ 64)];
                float sgn = (f0 < 64) ? -1.f : 1.f;
                float o0 = (me0 * cs.x + sgn * pr0 * sn.x) * scale;
                float o1 = (me1 * cs.y + sgn * pr1 * sn.y) * scale;
                uint32_t hi, lo;
                split_pair(o0, o1, hi, lo);
                ohi[orow + (f0 >> 1)] = hi;
                olo[orow + (f0 >> 1)] = lo;
            }
        }
    }
}

// GEMM + fused transpose+split epilogue for V projection
__global__ __launch_bounds__(256, 2)
void bgemm_vt_kernel(const uint32_t* __restrict__ Ahi, const uint32_t* __restrict__ Alo,
                     const uint32_t* __restrict__ Bhi, const uint32_t* __restrict__ Blo,
                     const float* __restrict__ bias,
                     uint32_t* __restrict__ vthi, uint32_t* __restrict__ vtlo) {
    extern __shared__ char gsm[];
    const uint32_t smem_base = (uint32_t)__cvta_generic_to_shared(gsm);
    const int tid = threadIdx.x;
    const int lane = tid & 31;
    const int warp = tid >> 5;
    const int wm = (warp >> 2) * 64;
    const int wn = (warp & 3) * 32;
    const int g = lane >> 2;
    const int t4 = lane & 3;
    const int bm = blockIdx.y * 128, bn = blockIdx.x * 128;

    float acc[4][4][4];
#pragma unroll
    for (int i = 0; i < 4; i++)
#pragma unroll
        for (int j = 0; j < 4; j++)
#pragma unroll
            for (int r = 0; r < 4; r++) acc[i][j][r] = 0.f;

    GEMM_MAINLOOP(Ahi, Alo, Bhi, Blo)

    float* sv = (float*)gsm;   // [row][133]
#pragma unroll
    for (int rt = 0; rt < 4; rt++) {
#pragma unroll
        for (int half = 0; half < 2; half++) {
            int r = wm + rt * 16 + g + half * 8;
#pragma unroll
            for (int ct = 0; ct < 4; ct++) {
                int f = wn + ct * 8 + 2 * t4;
                sv[r * 133 + f] = acc[rt][ct][2 * half] + bias[bn + f];
                sv[r * 133 + f + 1] = acc[rt][ct][2 * half + 1] + bias[bn + f + 1];
            }
        }
    }
    __syncthreads();

    const int b = bm >> 11;
    const int p0 = bm & 2047;
#pragma unroll
    for (int i = 0; i < 16; i++) {
        int f = warp + i * 8;
        long dst = ((long)(b * 2048 + bn + f)) * 1024 + (p0 >> 1);
#pragma unroll
        for (int j = 0; j < 2; j++) {
            int pp = lane + j * 32;
            uint32_t hi, lo;
            split_pair(sv[(2 * pp) * 133 + f], sv[(2 * pp + 1) * 133 + f], hi, lo);
            vthi[dst + pp] = hi;
            vtlo[dst + pp] = lo;
        }
    }
}

// ---------------- flash attention: 128 threads, q-tile 64, kv-tile 32, occ 2 -----
#define FL_KSLO 8704
#define FL_VSHI 17408
#define FL_VSLO 27648
#define FL_STAGE 37888
#define FL_SMEM  75776

__global__ __launch_bounds__(128, 2)
void flash_kernel(const uint32_t* __restrict__ qhi, const uint32_t* __restrict__ qlo,
                  const uint32_t* __restrict__ khi, const uint32_t* __restrict__ klo,
                  const uint32_t* __restrict__ vthi, const uint32_t* __restrict__ vtlo,
                  float* __restrict__ part, float* __restrict__ lsum) {
    extern __shared__ char fsm[];
    const int tid = threadIdx.x;
    const int lane = tid & 31, warp = tid >> 5;   // warp 0..3
    const int g = lane >> 2, t4 = lane & 3;
    const int qt = blockIdx.x, bh = blockIdx.y, z = blockIdx.z;
    const int b = bh >> 4, h = bh & 15;
    const int wm = warp * 16;
    const long qr0 = (long)b * 2048 + qt * 64;

    part += (long)z * 4096 * 2048;
    lsum += (long)z * 4096 * 16;

    const uint32_t smem_base = (uint32_t)__cvta_generic_to_shared(fsm);

    uint32_t qah[8][4], qal[8][4];
    {
        const uint32_t* qh0 = qhi + (qr0 + wm + g) * 1024 + h * 64;
        const uint32_t* qh8 = qhi + (qr0 + wm + g + 8) * 1024 + h * 64;
        const uint32_t* ql0 = qlo + (qr0 + wm + g) * 1024 + h * 64;
        const uint32_t* ql8 = qlo + (qr0 + wm + g + 8) * 1024 + h * 64;
#pragma unroll
        for (int fs = 0; fs < 8; fs++) {
            qah[fs][0] = qh0[8 * fs + t4];
            qah[fs][1] = qh8[8 * fs + t4];
            qah[fs][2] = qh0[8 * fs + 4 + t4];
            qah[fs][3] = qh8[8 * fs + 4 + t4];
            qal[fs][0] = ql0[8 * fs + t4];
            qal[fs][1] = ql8[8 * fs + t4];
            qal[fs][2] = ql0[8 * fs + 4 + t4];
            qal[fs][3] = ql8[8 * fs + 4 + t4];
        }
    }

    float acc_o[16][4];
#pragma unroll
    for (int nt = 0; nt < 16; nt++)
#pragma unroll
        for (int j = 0; j < 4; j++) acc_o[nt][j] = 0.f;
    float lrow[2] = {0.f, 0.f};

    const uint32_t* khb = khi + ((long)b * 2048) * 1024 + h * 64;
    const uint32_t* klb = klo + ((long)b * 2048) * 1024 + h * 64;
    const uint32_t* vhb = vthi + ((long)b * 2048 + h * 128) * 1024;
    const uint32_t* vlb = vtlo + ((long)b * 2048 + h * 128) * 1024;

    // kv chunks of 32 rows; z half = 32 chunks
    const int kb0 = z * 32, kb1 = kb0 + 32;

    auto prefetch = [&](int kb) {
        uint32_t sb = smem_base + (kb & 1) * FL_STAGE;
        const uint32_t* kh = khb + (long)kb * 32 * 1024;
        const uint32_t* kl = klb + (long)kb * 32 * 1024;
        // K: 32 rows x 64 pairs (hi+lo), stride 68
#pragma unroll
        for (int i = 0; i < 4; i++) {
            int c = tid + i * 128;
            int row = c >> 4, cc = (c & 15) * 4;
            cpa16(sb + (row * 68 + cc) * 4, kh + (long)row * 1024 + cc);
            cpa16(sb + FL_KSLO + (row * 68 + cc) * 4, kl + (long)row * 1024 + cc);
        }
        // V: 128 cols x 16 ppairs (hi+lo), stride 20
#pragma unroll
        for (int i = 0; i < 4; i++) {
            int c = tid + i * 128;
            int col = c >> 2, ci = (c & 3) * 4;
            cpa16(sb + FL_VSHI + (col * 20 + ci) * 4, vhb + (long)col * 1024 + kb * 16 + ci);
            cpa16(sb + FL_VSLO + (col * 20 + ci) * 4, vlb + (long)col * 1024 + kb * 16 + ci);
        }
        asm volatile("cp.async.commit_group;\n" ::: "memory");
    };

    prefetch(kb0);

    for (int kb = kb0; kb < kb1; kb++) {
        if (kb + 1 < kb1) {
            prefetch(kb + 1);
            asm volatile("cp.async.wait_group 1;\n" ::: "memory");
        } else {
            asm volatile("cp.async.wait_group 0;\n" ::: "memory");
        }
        __syncthreads();

        const char* stg = fsm + (kb & 1) * FL_STAGE;
        const uint32_t* ksh = (const uint32_t*)(stg);
        const uint32_t* ksl = (const uint32_t*)(stg + FL_KSLO);
        const uint32_t* vsh = (const uint32_t*)(stg + FL_VSHI);
        const uint32_t* vsl = (const uint32_t*)(stg + FL_VSLO);

        // ---- S = Q @ K^T (64 x 32) ----
        float sacc[4][4];
#pragma unroll
        for (int nt = 0; nt < 4; nt++)
#pragma unroll
            for (int j = 0; j < 4; j++) sacc[nt][j] = 0.f;

#pragma unroll
        for (int fs = 0; fs < 8; fs++) {
            uint32_t kb0h[4], kb1h[4], kb0l[4], kb1l[4];
#pragma unroll
            for (int nt = 0; nt < 4; nt++) {
                int o = (nt * 8 + g) * 68 + fs * 8 + t4;
                kb0h[nt] = ksh[o];
                kb1h[nt] = ksh[o + 4];
                kb0l[nt] = ksl[o];
                kb1l[nt] = ksl[o + 4];
            }
#pragma unroll
            for (int nt = 0; nt < 4; nt++)
                mma16816(sacc[nt], qah[fs][0], qah[fs][1], qah[fs][2], qah[fs][3], kb0h[nt], kb1h[nt]);
#pragma unroll
            for (int nt = 0; nt < 4; nt++)
                mma16816(sacc[nt], qah[fs][0], qah[fs][1], qah[fs][2], qah[fs][3], kb0l[nt], kb1l[nt]);
#pragma unroll
            for (int nt = 0; nt < 4; nt++)
                mma16816(sacc[nt], qal[fs][0], qal[fs][1], qal[fs][2], qal[fs][3], kb0h[nt], kb1h[nt]);
        }

        // ---- fixed-offset softmax ----
#pragma unroll
        for (int r = 0; r < 2; r++) {
            float rs = 0.f;
#pragma unroll
            for (int nt = 0; nt < 4; nt++) {
                float p0 = fexp2(sacc[nt][2 * r] - SOFF);
                float p1 = fexp2(sacc[nt][2 * r + 1] - SOFF);
                sacc[nt][2 * r] = p0;
                sacc[nt][2 * r + 1] = p1;
                rs += p0 + p1;
            }
            rs += __shfl_xor_sync(0xffffffffu, rs, 1);
            rs += __shfl_xor_sync(0xffffffffu, rs, 2);
            lrow[r] += rs;
        }

        // ---- O += P @ V (64 x 128), k=32 -> two k16 steps ----
#pragma unroll
        for (int s = 0; s < 2; s++) {
            uint32_t ph[4], pl[4];
            {
                uint32_t h0, l0;
                split_pair(sacc[2 * s][0], sacc[2 * s][1], h0, l0);         ph[0] = h0; pl[0] = l0;
                split_pair(sacc[2 * s][2], sacc[2 * s][3], h0, l0);         ph[1] = h0; pl[1] = l0;
                split_pair(sacc[2 * s + 1][0], sacc[2 * s + 1][1], h0, l0); ph[2] = h0; pl[2] = l0;
                split_pair(sacc[2 * s + 1][2], sacc[2 * s + 1][3], h0, l0); ph[3] = h0; pl[3] = l0;
            }
#pragma unroll
            for (int nt = 0; nt < 16; nt++) {
                int o = (nt * 8 + g) * 20 + s * 8 + t4;
                uint32_t v0h = vsh[o], v1h = vsh[o + 4];
                uint32_t v0l = vsl[o], v1l = vsl[o + 4];
                mma16816(acc_o[nt], ph[0], ph[1], ph[2], ph[3], v0h, v1h);
                mma16816(acc_o[nt], pl[0], pl[1], pl[2], pl[3], v0h, v1h);
                mma16816(acc_o[nt], ph[0], ph[1], ph[2], ph[3], v0l, v1l);
            }
        }
        __syncthreads();
    }

    float* p0 = part + (qr0 + wm + g) * 2048 + h * 128;
    float* p8 = part + (qr0 + wm + g + 8) * 2048 + h * 128;
#pragma unroll
    for (int nt = 0; nt < 16; nt++) {
        int col = nt * 8 + 2 * t4;
        *(float2*)(p0 + col) = make_float2(acc_o[nt][0], acc_o[nt][1]);
        *(float2*)(p8 + col) = make_float2(acc_o[nt][2], acc_o[nt][3]);
    }
    if (t4 == 0) {
        lsum[(qr0 + wm + g) * 16 + h] = lrow[0];
        lsum[(qr0 + wm + g + 8) * 16 + h] = lrow[1];
    }
}

// ---------------- combine partials (vectorized) -----------------------------------
__global__ void combine_kernel(const float* __restrict__ part, const float* __restrict__ lsum,
                               uint32_t* __restrict__ ahi, uint32_t* __restrict__ alo) {
#pragma unroll
    for (int j = 0; j < 2; j++) {
        long idx = (long)blockIdx.x * 512 + j * 256 + threadIdx.x;
        int row = (int)(idx >> 9);
        int h = ((int)(idx * 2) & 1023) >> 6;
        float l = lsum[row * 16 + h] + lsum[4096 * 16 + row * 16 + h];
        float inv = 1.f / l;
        float4 a = ((const float4*)part)[idx];
        float4 b = ((const float4*)(part + (long)4096 * 2048))[idx];
        uint2 hi2, lo2;
        split_pair((a.x + b.x) * inv, (a.y + b.y) * inv, hi2.x, lo2.x);
        split_pair((a.z + b.z) * inv, (a.w + b.w) * inv, hi2.y, lo2.y);
        ((uint2*)ahi)[idx] = hi2;
        ((uint2*)alo)[idx] = lo2;
    }
}

// ---------------- host orchestration ----------------------------------------------
extern "C" void kernel_launch(void* const* d_in, const int* in_sizes, int n_in,
                              void* d_out, int out_size) {
    const float* xq = (const float*)d_in[0];
    const float* xk = (const float*)d_in[1];
    const float* xv = (const float*)d_in[2];
    const float* WQ = (const float*)d_in[3];
    const float* WK = (const float*)d_in[4];
    const float* WV = (const float*)d_in[5];
    const float* WO = (const float*)d_in[6];
    const float* bQ = (const float*)d_in[7];
    const float* bK = (const float*)d_in[8];
    const float* bV = (const float*)d_in[9];
    const float* bO = (const float*)d_in[10];
    const float* qw = (const float*)d_in[11];
    const float* kw = (const float*)d_in[12];
    float* out = (float*)d_out;

    float *ct, *st, *part, *lsum;
    uint32_t *xqhi, *xqlo, *xkhi, *xklo, *xvhi, *xvlo;
    uint32_t *w0hi, *w0lo, *w1hi, *w1lo, *w2hi, *w2lo, *wohi, *wolo;
    uint32_t *qhi, *qlo, *khi, *klo, *vthi, *vtlo, *ahi, *alo;
    cudaGetSymbolAddress((void**)&ct, g_cos);
    cudaGetSymbolAddress((void**)&st, g_sin);
    cudaGetSymbolAddress((void**)&part, g_part);
    cudaGetSymbolAddress((void**)&lsum, g_lsum);
    cudaGetSymbolAddress((void**)&xqhi, g_xqhi);
    cudaGetSymbolAddress((void**)&xqlo, g_xqlo);
    cudaGetSymbolAddress((void**)&xkhi, g_xkhi);
    cudaGetSymbolAddress((void**)&xklo, g_xklo);
    cudaGetSymbolAddress((void**)&xvhi, g_xvhi);
    cudaGetSymbolAddress((void**)&xvlo, g_xvlo);
    cudaGetSymbolAddress((void**)&w0hi, g_w0hi);
    cudaGetSymbolAddress((void**)&w0lo, g_w0lo);
    cudaGetSymbolAddress((void**)&w1hi, g_w1hi);
    cudaGetSymbolAddress((void**)&w1lo, g_w1lo);
    cudaGetSymbolAddress((void**)&w2hi, g_w2hi);
    cudaGetSymbolAddress((void**)&w2lo, g_w2lo);
    cudaGetSymbolAddress((void**)&wohi, g_wohi);
    cudaGetSymbolAddress((void**)&wolo, g_wolo);
    cudaGetSymbolAddress((void**)&qhi, g_qhi);
    cudaGetSymbolAddress((void**)&qlo, g_qlo);
    cudaGetSymbolAddress((void**)&khi, g_khi);
    cudaGetSymbolAddress((void**)&klo, g_klo);
    cudaGetSymbolAddress((void**)&vthi, g_vthi);
    cudaGetSymbolAddress((void**)&vtlo, g_vtlo);
    cudaGetSymbolAddress((void**)&ahi, g_ahi);
    cudaGetSymbolAddress((void**)&alo, g_alo);

    cudaFuncSetAttribute(flash_kernel, cudaFuncAttributeMaxDynamicSharedMemorySize, FL_SMEM);
    cudaFuncSetAttribute(bgemm2_kernel, cudaFuncAttributeMaxDynamicSharedMemorySize, G2_SMEM);
    cudaFuncSetAttribute(bgemm_nr_kernel, cudaFuncAttributeMaxDynamicSharedMemorySize, G2_SMEM);
    cudaFuncSetAttribute(bgemm_vt_kernel, cudaFuncAttributeMaxDynamicSharedMemorySize, G2_SMEM);

    rope_table_kernel<<<(2048 * 64 + 255) / 256, 256>>>(ct, st);

    // pre-split inputs + weights
    dim3 gS(2048, 1, 3);
    split_rows3_kernel<<<gS, 256>>>(xq, xk, xv, xqhi, xqlo, xkhi, xklo, xvhi, xvlo);
    dim3 gW(1024, 1, 3);
    wsplit3_kernel<<<gW, 256>>>(WQ, WK, WV, w0hi, w0lo, w1hi, w1lo, w2hi, w2lo);
    wosplit_kernel<<<1024, 256>>>(WO, wohi, wolo);

    // Q,K projections with fused RMSNorm+RoPE+split epilogue
    dim3 gQK(16, 32, 2);
    bgemm_nr_kernel<<<gQK, 256, G2_SMEM>>>(
        xqhi, xqlo, w0hi, w0lo, bQ, qw,
        xkhi, xklo, w1hi, w1lo, bK, kw,
        ct, st, qhi, qlo, khi, klo);

    // V projection with fused transpose+split epilogue
    dim3 gVP(16, 32);
    bgemm_vt_kernel<<<gVP, 256, G2_SMEM>>>(xvhi, xvlo, w2hi, w2lo, bV, vthi, vtlo);

    // flash attention: 64-row q-tiles, 32-row kv-tiles, occ 2; then combine
    dim3 gF(32, 32, 2);
    flash_kernel<<<gF, 128, FL_SMEM>>>(qhi, qlo, khi, klo, vthi, vtlo, part, lsum);
    combine_kernel<<<4096, 256>>>(part, lsum, ahi, alo);

    // output projection
    dim3 gProj(16, 32);
    bgemm2_kernel<<<gProj, 256, G2_SMEM>>>(ahi, alo, wohi, wolo, out, bO);
}

// round 17
// speedup vs baseline: 1.0515x; 1.0515x over previous
#include <cuda_runtime.h>
#include <cuda_bf16.h>
#include <cstdint>
#include <math.h>

#define BB 2
#define SS 2048
#define DD 2048
#define HH 16
#define FF 128
#define EPSV 1e-6f

#define QSCALE 0.1275174431f
#define SOFF 16.5f

// ---------------- scratch (static device memory; no allocations) ----------------
__device__ float g_cos[2048 * 64];
__device__ float g_sin[2048 * 64];
__device__ uint32_t g_xqhi[4096 * 1024];
__device__ uint32_t g_xqlo[4096 * 1024];
__device__ uint32_t g_xkhi[4096 * 1024];
__device__ uint32_t g_xklo[4096 * 1024];
__device__ uint32_t g_xvhi[4096 * 1024];
__device__ uint32_t g_xvlo[4096 * 1024];
__device__ uint32_t g_w0hi[1024 * 2048];
__device__ uint32_t g_w0lo[1024 * 2048];
__device__ uint32_t g_w1hi[1024 * 2048];
__device__ uint32_t g_w1lo[1024 * 2048];
__device__ uint32_t g_w2hi[1024 * 2048];
__device__ uint32_t g_w2lo[1024 * 2048];
__device__ uint32_t g_wohi[1024 * 2048];
__device__ uint32_t g_wolo[1024 * 2048];
__device__ uint32_t g_qhi[4096 * 1024];
__device__ uint32_t g_qlo[4096 * 1024];
__device__ uint32_t g_khi[4096 * 1024];
__device__ uint32_t g_klo[4096 * 1024];
__device__ uint32_t g_vthi[2 * 2048 * 1024];
__device__ uint32_t g_vtlo[2 * 2048 * 1024];
__device__ float g_part[2 * 4096 * 2048];
__device__ float g_lsum[2 * 4096 * 16];
__device__ uint32_t g_ahi[4096 * 1024];
__device__ uint32_t g_alo[4096 * 1024];

// ---------------- helpers ---------------------------------------------------------
__device__ __forceinline__ uint32_t pack2(__nv_bfloat16 a, __nv_bfloat16 b) {
    __nv_bfloat162 h2;
    h2.x = a; h2.y = b;
    return *reinterpret_cast<uint32_t*>(&h2);
}

__device__ __forceinline__ void split_pair(float e0, float e1, uint32_t& hi, uint32_t& lo) {
    __nv_bfloat16 h0 = __float2bfloat16_rn(e0);
    __nv_bfloat16 h1 = __float2bfloat16_rn(e1);
    float l0 = e0 - __bfloat162float(h0);
    float l1 = e1 - __bfloat162float(h1);
    hi = pack2(h0, h1);
    lo = pack2(__float2bfloat16_rn(l0), __float2bfloat16_rn(l1));
}

__device__ __forceinline__ float fexp2(float x) {
    float r;
    asm("ex2.approx.f32 %0, %1;" : "=f"(r) : "f"(x));
    return r;
}

__device__ __forceinline__ void mma16816(float* c, uint32_t a0, uint32_t a1, uint32_t a2,
                                         uint32_t a3, uint32_t b0, uint32_t b1) {
    asm volatile(
        "mma.sync.aligned.m16n8k16.row.col.f32.bf16.bf16.f32 "
        "{%0,%1,%2,%3},{%4,%5,%6,%7},{%8,%9},{%0,%1,%2,%3};\n"
        : "+f"(c[0]), "+f"(c[1]), "+f"(c[2]), "+f"(c[3])
        : "r"(a0), "r"(a1), "r"(a2), "r"(a3), "r"(b0), "r"(b1));
}

__device__ __forceinline__ void cpa16(uint32_t dst, const void* src) {
    asm volatile("cp.async.cg.shared.global [%0], [%1], 16;\n" :: "r"(dst), "l"(src));
}

// ---------------- RoPE table -----------------------------------------------------
__global__ void rope_table_kernel(float* __restrict__ cosT, float* __restrict__ sinT) {
    int idx = blockIdx.x * 256 + threadIdx.x;
    if (idx >= 2048 * 64) return;
    int p = idx / 64, i = idx % 64;
    float freq = (float)(1.0 / pow(10000.0, (double)i / 64.0));
    float a = (float)p * freq;
    cosT[idx] = (float)cos((double)a);
    sinT[idx] = (float)sin((double)a);
}

// ---------------- vectorized pre-split kernels -----------------------------------
__global__ void split_rows3_kernel(const float* __restrict__ x0, const float* __restrict__ x1,
                                   const float* __restrict__ x2,
                                   uint32_t* __restrict__ h0, uint32_t* __restrict__ l0,
                                   uint32_t* __restrict__ h1, uint32_t* __restrict__ l1,
                                   uint32_t* __restrict__ h2, uint32_t* __restrict__ l2) {
    int s = blockIdx.z;
    const float4* x = (const float4*)((s == 0) ? x0 : (s == 1) ? x1 : x2);
    uint2* xh = (uint2*)((s == 0) ? h0 : (s == 1) ? h1 : h2);
    uint2* xl = (uint2*)((s == 0) ? l0 : (s == 1) ? l1 : l2);
    int base = blockIdx.x * 1024 + threadIdx.x;
    float4 v[4];
#pragma unroll
    for (int j = 0; j < 4; j++) v[j] = x[base + j * 256];
#pragma unroll
    for (int j = 0; j < 4; j++) {
        uint2 hi, lo;
        split_pair(v[j].x, v[j].y, hi.x, lo.x);
        split_pair(v[j].z, v[j].w, hi.y, lo.y);
        xh[base + j * 256] = hi;
        xl[base + j * 256] = lo;
    }
}

__global__ void wsplit3_kernel(const float* __restrict__ W0, const float* __restrict__ W1,
                               const float* __restrict__ W2,
                               uint32_t* __restrict__ h0, uint32_t* __restrict__ l0,
                               uint32_t* __restrict__ h1, uint32_t* __restrict__ l1,
                               uint32_t* __restrict__ h2, uint32_t* __restrict__ l2) {
    int s = blockIdx.z;
    const float* W = (s == 0) ? W0 : (s == 1) ? W1 : W2;
    uint32_t* wh = (s == 0) ? h0 : (s == 1) ? h1 : h2;
    uint32_t* wl = (s == 0) ? l0 : (s == 1) ? l1 : l2;
    int T = blockIdx.x * 256 + threadIdx.x;
    int n4 = T & 511, kp2 = T >> 9;
    int n = n4 * 4, h = n >> 7, f = n & 127;
    const float* base = W + ((long)h * 2048 + kp2 * 4) * 128 + f;
    float4 r0 = *(const float4*)(base);
    float4 r1 = *(const float4*)(base + 128);
    float4 r2 = *(const float4*)(base + 256);
    float4 r3 = *(const float4*)(base + 384);
    uint4 ha, la, hb, lb;
    split_pair(r0.x, r1.x, ha.x, la.x);
    split_pair(r0.y, r1.y, ha.y, la.y);
    split_pair(r0.z, r1.z, ha.z, la.z);
    split_pair(r0.w, r1.w, ha.w, la.w);
    split_pair(r2.x, r3.x, hb.x, lb.x);
    split_pair(r2.y, r3.y, hb.y, lb.y);
    split_pair(r2.z, r3.z, hb.z, lb.z);
    split_pair(r2.w, r3.w, hb.w, lb.w);
    long o0 = (long)(kp2 * 2) * 2048 + n;
    *(uint4*)&wh[o0] = ha;
    *(uint4*)&wl[o0] = la;
    *(uint4*)&wh[o0 + 2048] = hb;
    *(uint4*)&wl[o0 + 2048] = lb;
}

__global__ void wosplit_kernel(const float* __restrict__ WO,
                               uint32_t* __restrict__ whi, uint32_t* __restrict__ wlo) {
    int T = blockIdx.x * 256 + threadIdx.x;
    int m4 = T & 511, kp2 = T >> 9;
    int m = m4 * 4;
    const float* base = WO + (long)(kp2 * 4) * 2048 + m;
    float4 r0 = *(const float4*)(base);
    float4 r1 = *(const float4*)(base + 2048);
    float4 r2 = *(const float4*)(base + 4096);
    float4 r3 = *(const float4*)(base + 6144);
    uint4 ha, la, hb, lb;
    split_pair(r0.x, r1.x, ha.x, la.x);
    split_pair(r0.y, r1.y, ha.y, la.y);
    split_pair(r0.z, r1.z, ha.z, la.z);
    split_pair(r0.w, r1.w, ha.w, la.w);
    split_pair(r2.x, r3.x, hb.x, lb.x);
    split_pair(r2.y, r3.y, hb.y, lb.y);
    split_pair(r2.z, r3.z, hb.z, lb.z);
    split_pair(r2.w, r3.w, hb.w, lb.w);
    long o0 = (long)(kp2 * 2) * 2048 + m;
    *(uint4*)&whi[o0] = ha;
    *(uint4*)&wlo[o0] = la;
    *(uint4*)&whi[o0 + 2048] = hb;
    *(uint4*)&wlo[o0 + 2048] = lb;
}

// ---------------- GEMM config ------------------------------------------------------
#define G2_AS_LO 10240
#define G2_BS_HI 20480
#define G2_BS_LO 29184
#define G2_STAGE 37888
#define G2_SMEM  75776

#define GEMM_MAINLOOP(Ahi, Alo, Bhi, Blo)                                                   \
    auto prefetch = [&](int t) {                                                            \
        uint32_t sb = smem_base + (t & 1) * G2_STAGE;                                       \
        _Pragma("unroll")                                                                   \
        for (int i = 0; i < 2; i++) {                                                       \
            int c = tid + i * 256;                                                          \
            int row = c >> 2, q4 = (c & 3) * 4;                                             \
            cpa16(sb + (row * 20 + q4) * 4, Ahi + (long)(bm + row) * 1024 + t * 16 + q4);   \
            cpa16(sb + G2_AS_LO + (row * 20 + q4) * 4,                                      \
                  Alo + (long)(bm + row) * 1024 + t * 16 + q4);                             \
        }                                                                                   \
        _Pragma("unroll")                                                                   \
        for (int i = 0; i < 2; i++) {                                                       \
            int c = tid + i * 256;                                                          \
            int kp = c >> 5, n4 = (c & 31) * 4;                                             \
            cpa16(sb + G2_BS_HI + (kp * 136 + n4) * 4,                                      \
                  Bhi + (long)(t * 16 + kp) * 2048 + bn + n4);                              \
            cpa16(sb + G2_BS_LO + (kp * 136 + n4) * 4,                                      \
                  Blo + (long)(t * 16 + kp) * 2048 + bn + n4);                              \
        }                                                                                   \
        asm volatile("cp.async.commit_group;\n" ::: "memory");                              \
    };                                                                                      \
    prefetch(0);                                                                            \
    for (int t = 0; t < 64; t++) {                                                          \
        if (t + 1 < 64) {                                                                   \
            prefetch(t + 1);                                                                \
            asm volatile("cp.async.wait_group 1;\n" ::: "memory");                          \
        } else {                                                                            \
            asm volatile("cp.async.wait_group 0;\n" ::: "memory");                          \
        }                                                                                   \
        __syncthreads();                                                                    \
        const uint32_t* ash = (const uint32_t*)(gsm + (t & 1) * G2_STAGE);                  \
        const uint32_t* asl = (const uint32_t*)(gsm + (t & 1) * G2_STAGE + G2_AS_LO);       \
        const uint32_t* bsh = (const uint32_t*)(gsm + (t & 1) * G2_STAGE + G2_BS_HI);       \
        const uint32_t* bsl = (const uint32_t*)(gsm + (t & 1) * G2_STAGE + G2_BS_LO);       \
        _Pragma("unroll")                                                                   \
        for (int ks = 0; ks < 2; ks++) {                                                    \
            const int kp0 = ks * 8 + t4;                                                    \
            uint32_t bh0[4], bh1[4], bl0[4], bl1[4];                                        \
            _Pragma("unroll")                                                               \
            for (int ct = 0; ct < 4; ct++) {                                                \
                int col = wn + ct * 8 + g;                                                  \
                bh0[ct] = bsh[kp0 * 136 + col];                                             \
                bh1[ct] = bsh[(kp0 + 4) * 136 + col];                                       \
                bl0[ct] = bsl[kp0 * 136 + col];                                             \
                bl1[ct] = bsl[(kp0 + 4) * 136 + col];                                       \
            }                                                                               \
            _Pragma("unroll")                                                               \
            for (int rt = 0; rt < 4; rt++) {                                                \
                int row = wm + rt * 16 + g;                                                 \
                uint32_t ah0 = ash[row * 20 + kp0];                                         \
                uint32_t ah1 = ash[(row + 8) * 20 + kp0];                                   \
                uint32_t ah2 = ash[row * 20 + kp0 + 4];                                     \
                uint32_t ah3 = ash[(row + 8) * 20 + kp0 + 4];                               \
                uint32_t al0 = asl[row * 20 + kp0];                                         \
                uint32_t al1 = asl[(row + 8) * 20 + kp0];                                   \
                uint32_t al2 = asl[row * 20 + kp0 + 4];                                     \
                uint32_t al3 = asl[(row + 8) * 20 + kp0 + 4];                               \
                _Pragma("unroll")                                                           \
                for (int ct = 0; ct < 4; ct++) {                                            \
                    mma16816(acc[rt][ct], ah0, ah1, ah2, ah3, bh0[ct], bh1[ct]);            \
                    mma16816(acc[rt][ct], ah0, ah1, ah2, ah3, bl0[ct], bl1[ct]);            \
                    mma16816(acc[rt][ct], al0, al1, al2, al3, bh0[ct], bh1[ct]);            \
                }                                                                           \
            }                                                                               \
        }                                                                                   \
        __syncthreads();                                                                    \
    }

// plain GEMM (fp32 out + bias): O projection
__global__ __launch_bounds__(256, 2)
void bgemm2_kernel(const uint32_t* __restrict__ Ahi, const uint32_t* __restrict__ Alo,
                   const uint32_t* __restrict__ Bhi, const uint32_t* __restrict__ Blo,
                   float* __restrict__ C, const float* __restrict__ bias) {
    extern __shared__ char gsm[];
    const uint32_t smem_base = (uint32_t)__cvta_generic_to_shared(gsm);
    const int tid = threadIdx.x;
    const int lane = tid & 31;
    const int warp = tid >> 5;
    const int wm = (warp >> 2) * 64;
    const int wn = (warp & 3) * 32;
    const int g = lane >> 2;
    const int t4 = lane & 3;
    const int bm = blockIdx.y * 128, bn = blockIdx.x * 128;

    float acc[4][4][4];
#pragma unroll
    for (int i = 0; i < 4; i++)
#pragma unroll
        for (int j = 0; j < 4; j++)
#pragma unroll
            for (int r = 0; r < 4; r++) acc[i][j][r] = 0.f;

    GEMM_MAINLOOP(Ahi, Alo, Bhi, Blo)

#pragma unroll
    for (int rt = 0; rt < 4; rt++) {
        int row0 = bm + wm + rt * 16 + g;
#pragma unroll
        for (int ct = 0; ct < 4; ct++) {
            int col0 = bn + wn + ct * 8 + 2 * t4;
            float b0 = bias[col0], b1 = bias[col0 + 1];
            float2 v0 = make_float2(acc[rt][ct][0] + b0, acc[rt][ct][1] + b1);
            float2 v1 = make_float2(acc[rt][ct][2] + b0, acc[rt][ct][3] + b1);
            *(float2*)(C + (long)row0 * 2048 + col0) = v0;
            *(float2*)(C + (long)(row0 + 8) * 2048 + col0) = v1;
        }
    }
}

// one merged QKV projection kernel:
//   z=0: Q GEMM + RMSNorm+RoPE+split epilogue
//   z=1: K GEMM + RMSNorm+RoPE+split epilogue
//   z=2: V GEMM + transpose+split epilogue
__global__ __launch_bounds__(256, 2)
void bgemm_qkv_kernel(const uint32_t* __restrict__ Aqhi, const uint32_t* __restrict__ Aqlo,
                      const uint32_t* __restrict__ Bqhi, const uint32_t* __restrict__ Bqlo,
                      const float* __restrict__ bq, const float* __restrict__ wq,
                      const uint32_t* __restrict__ Akhi, const uint32_t* __restrict__ Aklo,
                      const uint32_t* __restrict__ Bkhi, const uint32_t* __restrict__ Bklo,
                      const float* __restrict__ bk, const float* __restrict__ wk,
                      const uint32_t* __restrict__ Avhi, const uint32_t* __restrict__ Avlo,
                      const uint32_t* __restrict__ Bvhi, const uint32_t* __restrict__ Bvlo,
                      const float* __restrict__ bv,
                      const float* __restrict__ cosT, const float* __restrict__ sinT,
                      uint32_t* __restrict__ qhi, uint32_t* __restrict__ qlo,
                      uint32_t* __restrict__ khi, uint32_t* __restrict__ klo,
                      uint32_t* __restrict__ vthi, uint32_t* __restrict__ vtlo) {
    extern __shared__ char gsm[];
    __shared__ float rsum[128][4];
    const uint32_t smem_base = (uint32_t)__cvta_generic_to_shared(gsm);

    int z = blockIdx.z;
    const uint32_t* Ahi = (z == 0) ? Aqhi : (z == 1) ? Akhi : Avhi;
    const uint32_t* Alo = (z == 0) ? Aqlo : (z == 1) ? Aklo : Avlo;
    const uint32_t* Bhi = (z == 0) ? Bqhi : (z == 1) ? Bkhi : Bvhi;
    const uint32_t* Blo = (z == 0) ? Bqlo : (z == 1) ? Bklo : Bvlo;
    const float* bias = (z == 0) ? bq : (z == 1) ? bk : bv;

    const int tid = threadIdx.x;
    const int lane = tid & 31;
    const int warp = tid >> 5;
    const int wm = (warp >> 2) * 64;
    const int wn = (warp & 3) * 32;
    const int g = lane >> 2;
    const int t4 = lane & 3;
    const int bm = blockIdx.y * 128, bn = blockIdx.x * 128;

    float acc[4][4][4];
#pragma unroll
    for (int i = 0; i < 4; i++)
#pragma unroll
        for (int j = 0; j < 4; j++)
#pragma unroll
            for (int r = 0; r < 4; r++) acc[i][j][r] = 0.f;

    GEMM_MAINLOOP(Ahi, Alo, Bhi, Blo)

    if (z < 2) {
        // ---- RMSNorm + RoPE + split epilogue ----
        const float* w = z ? wk : wq;
        uint32_t* ohi = z ? khi : qhi;
        uint32_t* olo = z ? klo : qlo;
        const float scale = z ? 1.f : QSCALE;

        float ss[4][2];
#pragma unroll
        for (int rt = 0; rt < 4; rt++) {
#pragma unroll
            for (int half = 0; half < 2; half++) {
                float s = 0.f;
#pragma unroll
                for (int ct = 0; ct < 4; ct++) {
                    int col0 = bn + wn + ct * 8 + 2 * t4;
                    float v0 = acc[rt][ct][2 * half] + bias[col0];
                    float v1 = acc[rt][ct][2 * half + 1] + bias[col0 + 1];
                    acc[rt][ct][2 * half] = v0;
                    acc[rt][ct][2 * half + 1] = v1;
                    s += v0 * v0 + v1 * v1;
                }
                s += __shfl_xor_sync(0xffffffffu, s, 1);
                s += __shfl_xor_sync(0xffffffffu, s, 2);
                ss[rt][half] = s;
            }
        }
        if (t4 == 0) {
#pragma unroll
            for (int rt = 0; rt < 4; rt++) {
#pragma unroll
                for (int half = 0; half < 2; half++)
                    rsum[wm + rt * 16 + g + half * 8][warp & 3] = ss[rt][half];
            }
        }
        __syncthreads();

        float* sv = (float*)gsm;
#pragma unroll
        for (int rt = 0; rt < 4; rt++) {
#pragma unroll
            for (int half = 0; half < 2; half++) {
                int r = wm + rt * 16 + g + half * 8;
                float tot = rsum[r][0] + rsum[r][1] + rsum[r][2] + rsum[r][3];
                float inv = 1.f / (sqrtf(tot * (1.f / 128.f)) + EPSV);
#pragma unroll
                for (int ct = 0; ct < 4; ct++) {
                    int f = wn + ct * 8 + 2 * t4;
                    sv[r * 132 + f] = acc[rt][ct][2 * half] * inv * __ldg(&w[f]);
                    sv[r * 132 + f + 1] = acc[rt][ct][2 * half + 1] * inv * __ldg(&w[f + 1]);
                }
            }
        }
        __syncthreads();

        const int h = bn >> 7;
#pragma unroll
        for (int rt = 0; rt < 4; rt++) {
#pragma unroll
            for (int half = 0; half < 2; half++) {
                int r = wm + rt * 16 + g + half * 8;
                int p = (bm + r) & (SS - 1);
                long orow = (long)(bm + r) * 1024 + h * 64;
#pragma unroll
                for (int ct = 0; ct < 4; ct++) {
                    int f0 = wn + ct * 8 + 2 * t4;
                    int i0 = f0 & 63;
                    float2 cs = *(const float2*)(cosT + p * 64 + i0);
                    float2 sn = *(const float2*)(sinT + p * 64 + i0);
                    float me0 = sv[r * 132 + f0];
                    float me1 = sv[r * 132 + f0 + 1];
                    float pr0 = sv[r * 132 + (f0 ^ 64)];
                    float pr1 = sv[r * 132 + ((f0 + 1) ^ 64)];
                    float sgn = (f0 < 64) ? -1.f : 1.f;
                    float o0 = (me0 * cs.x + sgn * pr0 * sn.x) * scale;
                    float o1 = (me1 * cs.y + sgn * pr1 * sn.y) * scale;
                    uint32_t hi, lo;
                    split_pair(o0, o1, hi, lo);
                    ohi[orow + (f0 >> 1)] = hi;
                    olo[orow + (f0 >> 1)] = lo;
                }
            }
        }
    } else {
        // ---- V: transpose + split epilogue ----
        float* sv = (float*)gsm;   // [row][133]
#pragma unroll
        for (int rt = 0; rt < 4; rt++) {
#pragma unroll
            for (int half = 0; half < 2; half++) {
                int r = wm + rt * 16 + g + half * 8;
#pragma unroll
                for (int ct = 0; ct < 4; ct++) {
                    int f = wn + ct * 8 + 2 * t4;
                    sv[r * 133 + f] = acc[rt][ct][2 * half] + bias[bn + f];
                    sv[r * 133 + f + 1] = acc[rt][ct][2 * half + 1] + bias[bn + f + 1];
                }
            }
        }
        __syncthreads();

        const int b = bm >> 11;
        const int p0 = bm & 2047;
#pragma unroll
        for (int i = 0; i < 16; i++) {
            int f = warp + i * 8;
            long dst = ((long)(b * 2048 + bn + f)) * 1024 + (p0 >> 1);
#pragma unroll
            for (int j = 0; j < 2; j++) {
                int pp = lane + j * 32;
                uint32_t hi, lo;
                split_pair(sv[(2 * pp) * 133 + f], sv[(2 * pp + 1) * 133 + f], hi, lo);
                vthi[dst + pp] = hi;
                vtlo[dst + pp] = lo;
            }
        }
    }
}

// ---------------- flash attention (R14 config): 256 thr, q128, kv64, 2-stage -----
#define FL_KSLO 17408
#define FL_VSHI 34816
#define FL_VSLO 53248
#define FL_STAGE 71680
#define FL_SMEM  143360

__global__ __launch_bounds__(256, 1)
void flash_kernel(const uint32_t* __restrict__ qhi, const uint32_t* __restrict__ qlo,
                  const uint32_t* __restrict__ khi, const uint32_t* __restrict__ klo,
                  const uint32_t* __restrict__ vthi, const uint32_t* __restrict__ vtlo,
                  float* __restrict__ part, float* __restrict__ lsum) {
    extern __shared__ char fsm[];
    const int tid = threadIdx.x;
    const int lane = tid & 31, warp = tid >> 5;
    const int g = lane >> 2, t4 = lane & 3;
    const int qt = blockIdx.x, bh = blockIdx.y, z = blockIdx.z;
    const int b = bh >> 4, h = bh & 15;
    const int wm = warp * 16;
    const long qr0 = (long)b * 2048 + qt * 128;

    part += (long)z * 4096 * 2048;
    lsum += (long)z * 4096 * 16;

    const uint32_t smem_base = (uint32_t)__cvta_generic_to_shared(fsm);

    uint32_t qah[8][4], qal[8][4];
    {
        const uint32_t* qh0 = qhi + (qr0 + wm + g) * 1024 + h * 64;
        const uint32_t* qh8 = qhi + (qr0 + wm + g + 8) * 1024 + h * 64;
        const uint32_t* ql0 = qlo + (qr0 + wm + g) * 1024 + h * 64;
        const uint32_t* ql8 = qlo + (qr0 + wm + g + 8) * 1024 + h * 64;
#pragma unroll
        for (int fs = 0; fs < 8; fs++) {
            qah[fs][0] = qh0[8 * fs + t4];
            qah[fs][1] = qh8[8 * fs + t4];
            qah[fs][2] = qh0[8 * fs + 4 + t4];
            qah[fs][3] = qh8[8 * fs + 4 + t4];
            qal[fs][0] = ql0[8 * fs + t4];
            qal[fs][1] = ql8[8 * fs + t4];
            qal[fs][2] = ql0[8 * fs + 4 + t4];
            qal[fs][3] = ql8[8 * fs + 4 + t4];
        }
    }

    float acc_o[16][4];
#pragma unroll
    for (int nt = 0; nt < 16; nt++)
#pragma unroll
        for (int j = 0; j < 4; j++) acc_o[nt][j] = 0.f;
    float lrow[2] = {0.f, 0.f};

    const uint32_t* khb = khi + ((long)b * 2048) * 1024 + h * 64;
    const uint32_t* klb = klo + ((long)b * 2048) * 1024 + h * 64;
    const uint32_t* vhb = vthi + ((long)b * 2048 + h * 128) * 1024;
    const uint32_t* vlb = vtlo + ((long)b * 2048 + h * 128) * 1024;

    const int kb0 = z * 16, kb1 = kb0 + 16;

    auto prefetch = [&](int kb) {
        uint32_t sb = smem_base + (kb & 1) * FL_STAGE;
        const uint32_t* kh = khb + (long)kb * 64 * 1024;
        const uint32_t* kl = klb + (long)kb * 64 * 1024;
#pragma unroll
        for (int i = 0; i < 4; i++) {
            int c = tid + i * 256;
            int row = c >> 4, cc = (c & 15) * 4;
            cpa16(sb + (row * 68 + cc) * 4, kh + (long)row * 1024 + cc);
            cpa16(sb + FL_KSLO + (row * 68 + cc) * 4, kl + (long)row * 1024 + cc);
        }
#pragma unroll
        for (int i = 0; i < 4; i++) {
            int c = tid + i * 256;
            int col = c >> 3, ci = (c & 7) * 4;
            cpa16(sb + FL_VSHI + (col * 36 + ci) * 4, vhb + (long)col * 1024 + kb * 32 + ci);
            cpa16(sb + FL_VSLO + (col * 36 + ci) * 4, vlb + (long)col * 1024 + kb * 32 + ci);
        }
        asm volatile("cp.async.commit_group;\n" ::: "memory");
    };

    prefetch(kb0);

    for (int kb = kb0; kb < kb1; kb++) {
        if (kb + 1 < kb1) {
            prefetch(kb + 1);
            asm volatile("cp.async.wait_group 1;\n" ::: "memory");
        } else {
            asm volatile("cp.async.wait_group 0;\n" ::: "memory");
        }
        __syncthreads();

        const char* stg = fsm + (kb & 1) * FL_STAGE;
        const uint32_t* ksh = (const uint32_t*)(stg);
        const uint32_t* ksl = (const uint32_t*)(stg + FL_KSLO);
        const uint32_t* vsh = (const uint32_t*)(stg + FL_VSHI);
        const uint32_t* vsl = (const uint32_t*)(stg + FL_VSLO);

        float sacc[8][4];
#pragma unroll
        for (int nt = 0; nt < 8; nt++)
#pragma unroll
            for (int j = 0; j < 4; j++) sacc[nt][j] = 0.f;

#pragma unroll
        for (int fs = 0; fs < 8; fs++) {
            uint32_t kb0h[8], kb1h[8], kb0l[8], kb1l[8];
#pragma unroll
            for (int nt = 0; nt < 8; nt++) {
                int o = (nt * 8 + g) * 68 + fs * 8 + t4;
                kb0h[nt] = ksh[o];
                kb1h[nt] = ksh[o + 4];
                kb0l[nt] = ksl[o];
                kb1l[nt] = ksl[o + 4];
            }
#pragma unroll
            for (int nt = 0; nt < 8; nt++) {
                mma16816(sacc[nt], qah[fs][0], qah[fs][1], qah[fs][2], qah[fs][3], kb0h[nt], kb1h[nt]);
                mma16816(sacc[nt], qah[fs][0], qah[fs][1], qah[fs][2], qah[fs][3], kb0l[nt], kb1l[nt]);
                mma16816(sacc[nt], qal[fs][0], qal[fs][1], qal[fs][2], qal[fs][3], kb0h[nt], kb1h[nt]);
            }
        }

#pragma unroll
        for (int r = 0; r < 2; r++) {
            float rs = 0.f;
#pragma unroll
            for (int nt = 0; nt < 8; nt++) {
                float p0 = fexp2(sacc[nt][2 * r] - SOFF);
                float p1 = fexp2(sacc[nt][2 * r + 1] - SOFF);
                sacc[nt][2 * r] = p0;
                sacc[nt][2 * r + 1] = p1;
                rs += p0 + p1;
            }
            rs += __shfl_xor_sync(0xffffffffu, rs, 1);
            rs += __shfl_xor_sync(0xffffffffu, rs, 2);
            lrow[r] += rs;
        }

#pragma unroll
        for (int s = 0; s < 4; s++) {
            uint32_t ph[4], pl[4];
            {
                uint32_t h0, l0;
                split_pair(sacc[2 * s][0], sacc[2 * s][1], h0, l0);         ph[0] = h0; pl[0] = l0;
                split_pair(sacc[2 * s][2], sacc[2 * s][3], h0, l0);         ph[1] = h0; pl[1] = l0;
                split_pair(sacc[2 * s + 1][0], sacc[2 * s + 1][1], h0, l0); ph[2] = h0; pl[2] = l0;
                split_pair(sacc[2 * s + 1][2], sacc[2 * s + 1][3], h0, l0); ph[3] = h0; pl[3] = l0;
            }
#pragma unroll
            for (int nt = 0; nt < 16; nt++) {
                int o = (nt * 8 + g) * 36 + s * 8 + t4;
                uint32_t v0h = vsh[o], v1h = vsh[o + 4];
                uint32_t v0l = vsl[o], v1l = vsl[o + 4];
                mma16816(acc_o[nt], ph[0], ph[1], ph[2], ph[3], v0h, v1h);
                mma16816(acc_o[nt], pl[0], pl[1], pl[2], pl[3], v0h, v1h);
                mma16816(acc_o[nt], ph[0], ph[1], ph[2], ph[3], v0l, v1l);
            }
        }
        __syncthreads();
    }

    float* p0 = part + (qr0 + wm + g) * 2048 + h * 128;
    float* p8 = part + (qr0 + wm + g + 8) * 2048 + h * 128;
#pragma unroll
    for (int nt = 0; nt < 16; nt++) {
        int col = nt * 8 + 2 * t4;
        *(float2*)(p0 + col) = make_float2(acc_o[nt][0], acc_o[nt][1]);
        *(float2*)(p8 + col) = make_float2(acc_o[nt][2], acc_o[nt][3]);
    }
    if (t4 == 0) {
        lsum[(qr0 + wm + g) * 16 + h] = lrow[0];
        lsum[(qr0 + wm + g + 8) * 16 + h] = lrow[1];
    }
}

// ---------------- combine partials (vectorized) -----------------------------------
__global__ void combine_kernel(const float* __restrict__ part, const float* __restrict__ lsum,
                               uint32_t* __restrict__ ahi, uint32_t* __restrict__ alo) {
#pragma unroll
    for (int j = 0; j < 2; j++) {
        long idx = (long)blockIdx.x * 512 + j * 256 + threadIdx.x;
        int row = (int)(idx >> 9);
        int h = ((int)(idx * 2) & 1023) >> 6;
        float l = lsum[row * 16 + h] + lsum[4096 * 16 + row * 16 + h];
        float inv = 1.f / l;
        float4 a = ((const float4*)part)[idx];
        float4 b = ((const float4*)(part + (long)4096 * 2048))[idx];
        uint2 hi2, lo2;
        split_pair((a.x + b.x) * inv, (a.y + b.y) * inv, hi2.x, lo2.x);
        split_pair((a.z + b.z) * inv, (a.w + b.w) * inv, hi2.y, lo2.y);
        ((uint2*)ahi)[idx] = hi2;
        ((uint2*)alo)[idx] = lo2;
    }
}

// ---------------- host orchestration ----------------------------------------------
extern "C" void kernel_launch(void* const* d_in, const int* in_sizes, int n_in,
                              void* d_out, int out_size) {
    const float* xq = (const float*)d_in[0];
    const float* xk = (const float*)d_in[1];
    const float* xv = (const float*)d_in[2];
    const float* WQ = (const float*)d_in[3];
    const float* WK = (const float*)d_in[4];
    const float* WV = (const float*)d_in[5];
    const float* WO = (const float*)d_in[6];
    const float* bQ = (const float*)d_in[7];
    const float* bK = (const float*)d_in[8];
    const float* bV = (const float*)d_in[9];
    const float* bO = (const float*)d_in[10];
    const float* qw = (const float*)d_in[11];
    const float* kw = (const float*)d_in[12];
    float* out = (float*)d_out;

    float *ct, *st, *part, *lsum;
    uint32_t *xqhi, *xqlo, *xkhi, *xklo, *xvhi, *xvlo;
    uint32_t *w0hi, *w0lo, *w1hi, *w1lo, *w2hi, *w2lo, *wohi, *wolo;
    uint32_t *qhi, *qlo, *khi, *klo, *vthi, *vtlo, *ahi, *alo;
    cudaGetSymbolAddress((void**)&ct, g_cos);
    cudaGetSymbolAddress((void**)&st, g_sin);
    cudaGetSymbolAddress((void**)&part, g_part);
    cudaGetSymbolAddress((void**)&lsum, g_lsum);
    cudaGetSymbolAddress((void**)&xqhi, g_xqhi);
    cudaGetSymbolAddress((void**)&xqlo, g_xqlo);
    cudaGetSymbolAddress((void**)&xkhi, g_xkhi);
    cudaGetSymbolAddress((void**)&xklo, g_xklo);
    cudaGetSymbolAddress((void**)&xvhi, g_xvhi);
    cudaGetSymbolAddress((void**)&xvlo, g_xvlo);
    cudaGetSymbolAddress((void**)&w0hi, g_w0hi);
    cudaGetSymbolAddress((void**)&w0lo, g_w0lo);
    cudaGetSymbolAddress((void**)&w1hi, g_w1hi);
    cudaGetSymbolAddress((void**)&w1lo, g_w1lo);
    cudaGetSymbolAddress((void**)&w2hi, g_w2hi);
    cudaGetSymbolAddress((void**)&w2lo, g_w2lo);
    cudaGetSymbolAddress((void**)&wohi, g_wohi);
    cudaGetSymbolAddress((void**)&wolo, g_wolo);
    cudaGetSymbolAddress((void**)&qhi, g_qhi);
    cudaGetSymbolAddress((void**)&qlo, g_qlo);
    cudaGetSymbolAddress((void**)&khi, g_khi);
    cudaGetSymbolAddress((void**)&klo, g_klo);
    cudaGetSymbolAddress((void**)&vthi, g_vthi);
    cudaGetSymbolAddress((void**)&vtlo, g_vtlo);
    cudaGetSymbolAddress((void**)&ahi, g_ahi);
    cudaGetSymbolAddress((void**)&alo, g_alo);

    cudaFuncSetAttribute(flash_kernel, cudaFuncAttributeMaxDynamicSharedMemorySize, FL_SMEM);
    cudaFuncSetAttribute(bgemm2_kernel, cudaFuncAttributeMaxDynamicSharedMemorySize, G2_SMEM);
    cudaFuncSetAttribute(bgemm_qkv_kernel, cudaFuncAttributeMaxDynamicSharedMemorySize, G2_SMEM);

    rope_table_kernel<<<(2048 * 64 + 255) / 256, 256>>>(ct, st);

    // pre-split inputs + weights
    dim3 gS(2048, 1, 3);
    split_rows3_kernel<<<gS, 256>>>(xq, xk, xv, xqhi, xqlo, xkhi, xklo, xvhi, xvlo);
    dim3 gW(1024, 1, 3);
    wsplit3_kernel<<<gW, 256>>>(WQ, WK, WV, w0hi, w0lo, w1hi, w1lo, w2hi, w2lo);
    wosplit_kernel<<<1024, 256>>>(WO, wohi, wolo);

    // Q,K,V projections in ONE launch (z: 0=Q, 1=K, 2=V), fused epilogues
    dim3 gQKV(16, 32, 3);
    bgemm_qkv_kernel<<<gQKV, 256, G2_SMEM>>>(
        xqhi, xqlo, w0hi, w0lo, bQ, qw,
        xkhi, xklo, w1hi, w1lo, bK, kw,
        xvhi, xvlo, w2hi, w2lo, bV,
        ct, st, qhi, qlo, khi, klo, vthi, vtlo);

    // flash attention: split-KV partials (R14 config), then combine
    dim3 gF(16, 32, 2);
    flash_kernel<<<gF, 256, FL_SMEM>>>(qhi, qlo, khi, klo, vthi, vtlo, part, lsum);
    combine_kernel<<<4096, 256>>>(part, lsum, ahi, alo);

    // output projection
    dim3 gProj(16, 32);
    bgemm2_kernel<<<gProj, 256, G2_SMEM>>>(ahi, alo, wohi, wolo, out, bO);
}